// round 9
// baseline (speedup 1.0000x reference)
#include <cuda_runtime.h>
#include <math.h>
#include <stdint.h>

// Problem constants
#define B_   8
#define S_   1024
#define H_   16
#define LAT_ 1024
#define D_   64

// ---------------------------------------------------------------------------
// Scratch (__device__ globals: allocation-free rule)
// ---------------------------------------------------------------------------
__device__ float g_Q[(size_t)B_ * H_ * S_ * D_];   // [bh, s, d]
__device__ float g_K[(size_t)B_ * H_ * S_ * D_];   // [bh, s, d]
__device__ float g_V[(size_t)B_ * H_ * S_ * D_];   // [bh, s, d]
__device__ float g_O[(size_t)B_ * S_ * H_ * D_];   // [b*s, h*d]

// ---------------------------------------------------------------------------
// mma.sync m16n8k8 tf32 helpers (compute_80+)
// Fragment maps (PTX ISA), g = lane>>2, t = lane&3:
//   A(16x8):  a0=(g,t) a1=(g+8,t) a2=(g,t+4) a3=(g+8,t+4)
//   B(8x8):   b0=(t,g) b1=(t+4,g)
//   D(16x8):  d0=(g,2t) d1=(g,2t+1) d2=(g+8,2t) d3=(g+8,2t+1)
// ---------------------------------------------------------------------------
__device__ __forceinline__ void mma_tf32(float* d, const uint32_t* a,
                                         uint32_t b0, uint32_t b1) {
    asm volatile(
        "mma.sync.aligned.m16n8k8.row.col.f32.tf32.tf32.f32 "
        "{%0,%1,%2,%3}, {%4,%5,%6,%7}, {%8,%9}, {%0,%1,%2,%3};"
        : "+f"(d[0]), "+f"(d[1]), "+f"(d[2]), "+f"(d[3])
        : "r"(a[0]), "r"(a[1]), "r"(a[2]), "r"(a[3]), "r"(b0), "r"(b1));
}

__device__ __forceinline__ float to_tf32(float x) {
    uint32_t u;
    asm("cvt.rna.tf32.f32 %0, %1;" : "=r"(u) : "f"(x));
    return __uint_as_float(u);
}

__device__ __forceinline__ float4 to_tf32_4(float4 v) {
    v.x = to_tf32(v.x); v.y = to_tf32(v.y);
    v.z = to_tf32(v.z); v.w = to_tf32(v.w);
    return v;
}

__device__ __forceinline__ uint32_t fbits(float x) { return __float_as_uint(x); }

// ---------------------------------------------------------------------------
// TF32 tensor-core GEMM (unchanged from round 8): C = A @ W + bias.
// Tile 128x128, BK=16, double-buffered smem, one sync per k-step.
// ---------------------------------------------------------------------------
#define AST 20
#define BST 136

template <int OUT_BHSD>
__global__ __launch_bounds__(256, 2)
void gemm_mma(const float* __restrict__ A, const float* __restrict__ W,
              const float* __restrict__ bias, float* __restrict__ C)
{
    __shared__ float As[2][128 * AST];
    __shared__ float Bs[2][16 * BST];

    const int tid  = threadIdx.x;
    const int lane = tid & 31;
    const int wid  = tid >> 5;
    const int g = lane >> 2, t = lane & 3;
    const int wm = (wid & 1) * 64;
    const int wn = (wid >> 1) * 32;
    const int m0 = blockIdx.y * 128;
    const int n0 = blockIdx.x * 128;

    const int aidx0 = tid,        aidx1 = tid + 256;
    const int arow0 = aidx0 >> 2, ac0 = (aidx0 & 3) * 4;
    const int arow1 = aidx1 >> 2, ac1 = (aidx1 & 3) * 4;
    const int brow0 = aidx0 >> 5, bc0 = (aidx0 & 31) * 4;
    const int brow1 = aidx1 >> 5, bc1 = (aidx1 & 31) * 4;
    const float* gA0 = A + (size_t)(m0 + arow0) * LAT_ + ac0;
    const float* gA1 = A + (size_t)(m0 + arow1) * LAT_ + ac1;
    const float* gB0 = W + (size_t)brow0 * LAT_ + n0 + bc0;
    const float* gB1 = W + (size_t)brow1 * LAT_ + n0 + bc1;

    float acc[4][4][4];
#pragma unroll
    for (int i = 0; i < 4; i++)
#pragma unroll
        for (int j = 0; j < 4; j++)
#pragma unroll
            for (int r = 0; r < 4; r++) acc[i][j][r] = 0.0f;

    {
        float4 a0 = *(const float4*)(gA0);
        float4 a1 = *(const float4*)(gA1);
        float4 b0 = *(const float4*)(gB0);
        float4 b1 = *(const float4*)(gB1);
        *(float4*)&As[0][arow0 * AST + ac0] = to_tf32_4(a0);
        *(float4*)&As[0][arow1 * AST + ac1] = to_tf32_4(a1);
        *(float4*)&Bs[0][brow0 * BST + bc0] = to_tf32_4(b0);
        *(float4*)&Bs[0][brow1 * BST + bc1] = to_tf32_4(b1);
    }
    float4 ra0 = *(const float4*)(gA0 + 16);
    float4 ra1 = *(const float4*)(gA1 + 16);
    float4 rb0 = *(const float4*)(gB0 + (size_t)16 * LAT_);
    float4 rb1 = *(const float4*)(gB1 + (size_t)16 * LAT_);
    __syncthreads();

    for (int kt = 0; kt < 64; kt++) {
        const int cur = kt & 1, nxt = cur ^ 1;
        if (kt < 63) {
            *(float4*)&As[nxt][arow0 * AST + ac0] = to_tf32_4(ra0);
            *(float4*)&As[nxt][arow1 * AST + ac1] = to_tf32_4(ra1);
            *(float4*)&Bs[nxt][brow0 * BST + bc0] = to_tf32_4(rb0);
            *(float4*)&Bs[nxt][brow1 * BST + bc1] = to_tf32_4(rb1);
        }
        if (kt < 62) {
            const int ko = (kt + 2) * 16;
            ra0 = *(const float4*)(gA0 + ko);
            ra1 = *(const float4*)(gA1 + ko);
            rb0 = *(const float4*)(gB0 + (size_t)ko * LAT_);
            rb1 = *(const float4*)(gB1 + (size_t)ko * LAT_);
        }

#pragma unroll
        for (int ks = 0; ks < 2; ks++) {
            uint32_t a[4][4], b[4][2];
#pragma unroll
            for (int i = 0; i < 4; i++) {
                int base = (wm + i * 16 + g) * AST + ks * 8 + t;
                a[i][0] = fbits(As[cur][base]);
                a[i][1] = fbits(As[cur][base + 8 * AST]);
                a[i][2] = fbits(As[cur][base + 4]);
                a[i][3] = fbits(As[cur][base + 8 * AST + 4]);
            }
#pragma unroll
            for (int j = 0; j < 4; j++) {
                int base = (ks * 8 + t) * BST + wn + j * 8 + g;
                b[j][0] = fbits(Bs[cur][base]);
                b[j][1] = fbits(Bs[cur][base + 4 * BST]);
            }
#pragma unroll
            for (int i = 0; i < 4; i++)
#pragma unroll
                for (int j = 0; j < 4; j++)
                    mma_tf32(acc[i][j], a[i], b[j][0], b[j][1]);
        }
        __syncthreads();
    }

#pragma unroll
    for (int i = 0; i < 4; i++) {
        int r0 = m0 + wm + i * 16 + g;
#pragma unroll
        for (int j = 0; j < 4; j++) {
            int n = n0 + wn + j * 8 + 2 * t;
            float2 bb = *(const float2*)&bias[n];
            float2 v0 = { acc[i][j][0] + bb.x, acc[i][j][1] + bb.y };
            float2 v1 = { acc[i][j][2] + bb.x, acc[i][j][3] + bb.y };
            if (!OUT_BHSD) {
                *(float2*)(C + (size_t)r0 * LAT_ + n)       = v0;
                *(float2*)(C + (size_t)(r0 + 8) * LAT_ + n) = v1;
            } else {
                int bi = r0 >> 10, s = r0 & 1023;
                int h = n >> 6, d = n & 63;
                *(float2*)(C + (((size_t)(bi * H_ + h)) * S_ + s) * D_ + d)     = v0;
                *(float2*)(C + (((size_t)(bi * H_ + h)) * S_ + s + 8) * D_ + d) = v1;
            }
        }
    }
}

// ---------------------------------------------------------------------------
// Tensor-core flash attention:
//   32 queries/warp (x2 B-fragment reuse), 2 CTAs/SM (regs capped at 128 via
//   32-key score chunks), shfl-built P fragments (no P smem round-trip).
// Block: 256 queries, 256 threads (8 warps); warp w owns rows [32w, 32w+32)
// as two m-tiles. Grid (S/256, B*H) = (4, 128).
// Smem (100352 B <= 114KB -> 2 CTAs/SM):
//   Qf 64KB frag-major | Kf 17KB | Vf 17KB (Q staged via 34KB transient x2).
// Per 64-key round: stage Kf/Vf once; process keys in two 32-key chunks
// (QK 8ks x 4nt -> softmax-chunk -> PV 4ksp x 8nt), scores s[4][4] per m-tile.
// exp2-domain softmax (scores pre-scaled by 0.125*log2 e).
// ---------------------------------------------------------------------------
#define QF_OFF   0
#define KF_OFF   65536
#define VF_OFF   (65536 + 17408)
#define QTMP_OFF 65536                  /* transient 34816B, overlays Kf/Vf */
#define ATTN_SMEM (65536 + 2 * 17408)   /* 100352 B */
#define SCL 0.1803368801111244f   /* 0.125 * log2(e) */

// Online-softmax update for one m-tile on a 32-key chunk c.
// sArr: s[4][4] scores (in place -> P). bits: 32-bit mask for the 64-key round.
#define SOFTMAX_CHUNK(sArr, bits, c, mr0, mr1, lr0, lr1, oArr)                 \
    do {                                                                       \
        float rm0 = -INFINITY, rm1 = -INFINITY;                                \
        _Pragma("unroll")                                                      \
        for (int nt = 0; nt < 4; nt++) {                                       \
            int bo = ((c) * 4 + nt) * 4;                                       \
            sArr[nt][0] = ((bits >> (bo + 0)) & 1u) ? sArr[nt][0] * SCL : -INFINITY; \
            sArr[nt][1] = ((bits >> (bo + 1)) & 1u) ? sArr[nt][1] * SCL : -INFINITY; \
            sArr[nt][2] = ((bits >> (bo + 2)) & 1u) ? sArr[nt][2] * SCL : -INFINITY; \
            sArr[nt][3] = ((bits >> (bo + 3)) & 1u) ? sArr[nt][3] * SCL : -INFINITY; \
            rm0 = fmaxf(rm0, fmaxf(sArr[nt][0], sArr[nt][1]));                 \
            rm1 = fmaxf(rm1, fmaxf(sArr[nt][2], sArr[nt][3]));                 \
        }                                                                      \
        _Pragma("unroll")                                                      \
        for (int off = 1; off <= 2; off <<= 1) {                               \
            rm0 = fmaxf(rm0, __shfl_xor_sync(0xffffffffu, rm0, off));          \
            rm1 = fmaxf(rm1, __shfl_xor_sync(0xffffffffu, rm1, off));          \
        }                                                                      \
        float mn0 = fmaxf(mr0, rm0), mn1 = fmaxf(mr1, rm1);                    \
        float c0 = (mn0 == -INFINITY) ? 1.0f : exp2f(mr0 - mn0);               \
        float c1 = (mn1 == -INFINITY) ? 1.0f : exp2f(mr1 - mn1);               \
        mr0 = mn0; mr1 = mn1;                                                  \
        float rs0 = 0.0f, rs1 = 0.0f;                                          \
        _Pragma("unroll")                                                      \
        for (int nt = 0; nt < 4; nt++) {                                       \
            float p0 = (sArr[nt][0] == -INFINITY) ? 0.0f : exp2f(sArr[nt][0] - mn0); \
            float p1 = (sArr[nt][1] == -INFINITY) ? 0.0f : exp2f(sArr[nt][1] - mn0); \
            float p2 = (sArr[nt][2] == -INFINITY) ? 0.0f : exp2f(sArr[nt][2] - mn1); \
            float p3 = (sArr[nt][3] == -INFINITY) ? 0.0f : exp2f(sArr[nt][3] - mn1); \
            sArr[nt][0] = p0; sArr[nt][1] = p1; sArr[nt][2] = p2; sArr[nt][3] = p3;  \
            rs0 += p0 + p1;  rs1 += p2 + p3;                                   \
        }                                                                      \
        _Pragma("unroll")                                                      \
        for (int off = 1; off <= 2; off <<= 1) {                               \
            rs0 += __shfl_xor_sync(0xffffffffu, rs0, off);                     \
            rs1 += __shfl_xor_sync(0xffffffffu, rs1, off);                     \
        }                                                                      \
        lr0 = lr0 * c0 + rs0;  lr1 = lr1 * c1 + rs1;                           \
        _Pragma("unroll")                                                      \
        for (int nt = 0; nt < 8; nt++) {                                       \
            oArr[nt][0] *= c0; oArr[nt][1] *= c0;                              \
            oArr[nt][2] *= c1; oArr[nt][3] *= c1;                              \
        }                                                                      \
    } while (0)

__global__ __launch_bounds__(256, 2)
void attn_mma_kernel(const int* __restrict__ mask, float* __restrict__ Og)
{
    extern __shared__ __align__(16) char smem[];
    float* Qf   = (float*)(smem + QF_OFF);
    float* Kf   = (float*)(smem + KF_OFF);
    float* Vf   = (float*)(smem + VF_OFF);
    float* Qtmp = (float*)(smem + QTMP_OFF);

    const int tid  = threadIdx.x;
    const int lane = tid & 31;
    const int wid  = tid >> 5;
    const int g = lane >> 2, t = lane & 3;
    const int qbase = blockIdx.x * 256;
    const int bh    = blockIdx.y;
    const int wq    = wid * 32;

    // --- Stage Q in two 128-row passes through the 34KB transient ---
    const float* Qp = g_Q + ((size_t)bh * S_ + qbase) * D_;
#pragma unroll
    for (int p = 0; p < 2; p++) {
#pragma unroll
        for (int it = 0; it < 8; it++) {
            int idx = tid + it * 256;          // 0..2047 over 128 rows
            int row = idx >> 4, c4 = (idx & 15) * 4;
            *(float4*)&Qtmp[row * 68 + c4] =
                to_tf32_4(*(const float4*)(Qp + (size_t)(p * 128 + row) * D_ + c4));
        }
        __syncthreads();
        if ((wid >> 2) == p) {
            int rbase = wq - p * 128;          // 0,32,64,96
#pragma unroll
            for (int m = 0; m < 2; m++)
#pragma unroll
                for (int ks = 0; ks < 8; ks++) {
                    int r = rbase + m * 16;
                    float q0 = Qtmp[(r + g) * 68 + ks * 8 + t];
                    float q1 = Qtmp[(r + g + 8) * 68 + ks * 8 + t];
                    float q2 = Qtmp[(r + g) * 68 + ks * 8 + t + 4];
                    float q3 = Qtmp[(r + g + 8) * 68 + ks * 8 + t + 4];
                    float4 f = { q0, q1, q2, q3 };
                    *(float4*)&Qf[wid * 2048 + m * 1024 + ks * 128 + lane * 4] = f;
                }
        }
        __syncthreads();
    }

    float mr[2][2] = { { -INFINITY, -INFINITY }, { -INFINITY, -INFINITY } };
    float lr[2][2] = { { 0.0f, 0.0f }, { 0.0f, 0.0f } };
    float o0[8][4], o1[8][4];
#pragma unroll
    for (int nt = 0; nt < 8; nt++)
#pragma unroll
        for (int r = 0; r < 4; r++) { o0[nt][r] = 0.0f; o1[nt][r] = 0.0f; }

    // V staging map (fixed per thread)
    const int vrp = tid >> 3, vc = tid & 7;
    const int vks = vrp >> 2, vt = vrp & 3, vr = vks * 8 + vt;

    // Shfl-P lane mapping (verified in round 8)
    const int srcA = (lane & 28) + (t >> 1);
    const int srcB = srcA + 2;
    const bool odd = (t & 1);

    for (int kt = 0; kt < 16; kt++) {
        const int kbase = kt * 64;

        // --- Mask: load + pack to 32 bits per m-tile (64 keys) ---
        uint32_t mb0 = 0, mb1 = 0;
        {
            const int* p0 = mask + ((size_t)bh * S_ + (qbase + wq + g)) * S_ + kbase;
            const int* p1 = p0 + 8 * S_;
            const int* p2 = p0 + 16 * S_;
            const int* p3 = p0 + 24 * S_;
#pragma unroll
            for (int nt = 0; nt < 8; nt++) {
                int2 a = *(const int2*)&p0[nt * 8 + 2 * t];
                int2 b = *(const int2*)&p1[nt * 8 + 2 * t];
                int2 c = *(const int2*)&p2[nt * 8 + 2 * t];
                int2 d = *(const int2*)&p3[nt * 8 + 2 * t];
                mb0 |= (uint32_t)(a.x != 0) << (nt * 4 + 0);
                mb0 |= (uint32_t)(a.y != 0) << (nt * 4 + 1);
                mb0 |= (uint32_t)(b.x != 0) << (nt * 4 + 2);
                mb0 |= (uint32_t)(b.y != 0) << (nt * 4 + 3);
                mb1 |= (uint32_t)(c.x != 0) << (nt * 4 + 0);
                mb1 |= (uint32_t)(c.y != 0) << (nt * 4 + 1);
                mb1 |= (uint32_t)(d.x != 0) << (nt * 4 + 2);
                mb1 |= (uint32_t)(d.y != 0) << (nt * 4 + 3);
            }
        }

        // --- Stage K in fragment-pair order: 2 items/thread ---
#pragma unroll
        for (int it = 0; it < 2; it++) {
            int item = tid + it * 256;          // 0..511
            int r = item >> 3, c = item & 7;
            const float* gk = g_K + ((size_t)bh * S_ + kbase + r) * D_ + c * 8;
            float4 v0 = to_tf32_4(*(const float4*)gk);
            float4 v1 = to_tf32_4(*(const float4*)(gk + 4));
            float* dst = Kf + ((r >> 3) * 8 + c) * 68 + (r & 7) * 8;
            float4 w0 = { v0.x, v1.x, v0.y, v1.y };
            float4 w1 = { v0.z, v1.z, v0.w, v1.w };
            *(float4*)(dst)     = w0;
            *(float4*)(dst + 4) = w1;
        }
        // --- Stage V: row pair (vr, vr+4), 8-col block vc ---
        {
            const float* gv = g_V + ((size_t)bh * S_ + kbase + vr) * D_ + vc * 8;
            float4 a0 = to_tf32_4(*(const float4*)gv);
            float4 a1 = to_tf32_4(*(const float4*)(gv + 4));
            float4 b0 = to_tf32_4(*(const float4*)(gv + 4 * D_));
            float4 b1 = to_tf32_4(*(const float4*)(gv + 4 * D_ + 4));
            float* dst = Vf + (vks * 8 + vc) * 68 + vt * 2;
            float2 p;
            p.x = a0.x; p.y = b0.x; *(float2*)(dst + 0)  = p;
            p.x = a0.y; p.y = b0.y; *(float2*)(dst + 8)  = p;
            p.x = a0.z; p.y = b0.z; *(float2*)(dst + 16) = p;
            p.x = a0.w; p.y = b0.w; *(float2*)(dst + 24) = p;
            p.x = a1.x; p.y = b1.x; *(float2*)(dst + 32) = p;
            p.x = a1.y; p.y = b1.y; *(float2*)(dst + 40) = p;
            p.x = a1.z; p.y = b1.z; *(float2*)(dst + 48) = p;
            p.x = a1.w; p.y = b1.w; *(float2*)(dst + 56) = p;
        }
        __syncthreads();

        // --- Two 32-key chunks per staged tile ---
#pragma unroll
        for (int c = 0; c < 2; c++) {
            // S = Q @ K^T for this chunk
            float s0[4][4], s1[4][4];
#pragma unroll
            for (int nt = 0; nt < 4; nt++)
#pragma unroll
                for (int r = 0; r < 4; r++) { s0[nt][r] = 0.0f; s1[nt][r] = 0.0f; }
#pragma unroll
            for (int ks = 0; ks < 8; ks++) {
                uint4 qf0 = *(const uint4*)&Qf[wid * 2048 + ks * 128 + lane * 4];
                uint4 qf1 = *(const uint4*)&Qf[wid * 2048 + 1024 + ks * 128 + lane * 4];
                uint32_t A0[4] = { qf0.x, qf0.y, qf0.z, qf0.w };
                uint32_t A1[4] = { qf1.x, qf1.y, qf1.z, qf1.w };
#pragma unroll
                for (int nt = 0; nt < 4; nt++) {
                    float2 kf = *(const float2*)&Kf[((c * 4 + nt) * 8 + ks) * 68 + lane * 2];
                    mma_tf32(s0[nt], A0, fbits(kf.x), fbits(kf.y));
                    mma_tf32(s1[nt], A1, fbits(kf.x), fbits(kf.y));
                }
            }

            // Online softmax on the chunk (scores -> P values in registers)
            SOFTMAX_CHUNK(s0, mb0, c, mr[0][0], mr[0][1], lr[0][0], lr[0][1], o0);
            SOFTMAX_CHUNK(s1, mb1, c, mr[1][0], mr[1][1], lr[1][0], lr[1][1], o1);

            // O += P @ V : P A-frags built by quad-shfl
#pragma unroll
            for (int ksp = 0; ksp < 4; ksp++) {
                float a0 = __shfl_sync(0xffffffffu, s0[ksp][0], srcA);
                float a1 = __shfl_sync(0xffffffffu, s0[ksp][1], srcA);
                float a2 = __shfl_sync(0xffffffffu, s0[ksp][2], srcA);
                float a3 = __shfl_sync(0xffffffffu, s0[ksp][3], srcA);
                float b0 = __shfl_sync(0xffffffffu, s0[ksp][0], srcB);
                float b1 = __shfl_sync(0xffffffffu, s0[ksp][1], srcB);
                float b2 = __shfl_sync(0xffffffffu, s0[ksp][2], srcB);
                float b3 = __shfl_sync(0xffffffffu, s0[ksp][3], srcB);
                uint32_t P0[4] = { fbits(odd ? a1 : a0), fbits(odd ? a3 : a2),
                                   fbits(odd ? b1 : b0), fbits(odd ? b3 : b2) };
                a0 = __shfl_sync(0xffffffffu, s1[ksp][0], srcA);
                a1 = __shfl_sync(0xffffffffu, s1[ksp][1], srcA);
                a2 = __shfl_sync(0xffffffffu, s1[ksp][2], srcA);
                a3 = __shfl_sync(0xffffffffu, s1[ksp][3], srcA);
                b0 = __shfl_sync(0xffffffffu, s1[ksp][0], srcB);
                b1 = __shfl_sync(0xffffffffu, s1[ksp][1], srcB);
                b2 = __shfl_sync(0xffffffffu, s1[ksp][2], srcB);
                b3 = __shfl_sync(0xffffffffu, s1[ksp][3], srcB);
                uint32_t P1[4] = { fbits(odd ? a1 : a0), fbits(odd ? a3 : a2),
                                   fbits(odd ? b1 : b0), fbits(odd ? b3 : b2) };
#pragma unroll
                for (int nt = 0; nt < 8; nt++) {
                    float2 vf = *(const float2*)&Vf[((c * 4 + ksp) * 8 + nt) * 68 + lane * 2];
                    mma_tf32(o0[nt], P0, fbits(vf.x), fbits(vf.y));
                    mma_tf32(o1[nt], P1, fbits(vf.x), fbits(vf.y));
                }
            }
        }
        __syncthreads();   // Kf/Vf reads done before next round's staging
    }

    // --- Final normalize + write [b*s][h*64+d] ---
    const int b = bh >> 4;
    const int h = bh & 15;
#pragma unroll
    for (int m = 0; m < 2; m++) {
        const int r0 = qbase + wq + m * 16 + g;
        float inv0 = 1.0f / lr[m][0], inv1 = 1.0f / lr[m][1];
        float (*oo)[4] = m ? o1 : o0;
#pragma unroll
        for (int nt = 0; nt < 8; nt++) {
            int col = h * D_ + nt * 8 + 2 * t;
            float2 v0 = { oo[nt][0] * inv0, oo[nt][1] * inv0 };
            float2 v1 = { oo[nt][2] * inv1, oo[nt][3] * inv1 };
            *(float2*)(Og + ((size_t)(b * S_ + r0)) * (H_ * D_) + col)     = v0;
            *(float2*)(Og + ((size_t)(b * S_ + r0 + 8)) * (H_ * D_) + col) = v1;
        }
    }
}

// ---------------------------------------------------------------------------
// Launch
// ---------------------------------------------------------------------------
extern "C" void kernel_launch(void* const* d_in, const int* in_sizes, int n_in,
                              void* d_out, int out_size)
{
    const float* input  = (const float*)d_in[0];
    const float* latent = (const float*)d_in[1];
    const int*   mask   = (const int*)d_in[2];
    const float* Wq = (const float*)d_in[3];
    const float* bq = (const float*)d_in[4];
    const float* Wk = (const float*)d_in[5];
    const float* bk = (const float*)d_in[6];
    const float* Wv = (const float*)d_in[7];
    const float* bv = (const float*)d_in[8];
    const float* Wo = (const float*)d_in[9];
    const float* bo = (const float*)d_in[10];
    float* out = (float*)d_out;

    float *qp, *kp, *vp, *op;
    cudaGetSymbolAddress((void**)&qp, g_Q);
    cudaGetSymbolAddress((void**)&kp, g_K);
    cudaGetSymbolAddress((void**)&vp, g_V);
    cudaGetSymbolAddress((void**)&op, g_O);

    cudaFuncSetAttribute(attn_mma_kernel,
                         cudaFuncAttributeMaxDynamicSharedMemorySize, ATTN_SMEM);

    dim3 gg(LAT_ / 128, (B_ * S_) / 128);   // (8, 64)
    gemm_mma<1><<<gg, 256>>>(latent, Wq, bq, qp);
    gemm_mma<1><<<gg, 256>>>(input,  Wk, bk, kp);
    gemm_mma<1><<<gg, 256>>>(input,  Wv, bv, vp);

    dim3 ga(S_ / 256, B_ * H_);             // (4, 128)
    attn_mma_kernel<<<ga, 256, ATTN_SMEM>>>(mask, op);

    gemm_mma<0><<<gg, 256>>>(op, Wo, bo, out);
}

// round 10
// speedup vs baseline: 1.2614x; 1.2614x over previous
#include <cuda_runtime.h>
#include <math.h>
#include <stdint.h>

// Problem constants
#define B_   8
#define S_   1024
#define H_   16
#define LAT_ 1024
#define D_   64

// ---------------------------------------------------------------------------
// Scratch (__device__ globals: allocation-free rule)
// ---------------------------------------------------------------------------
__device__ float g_Q[(size_t)B_ * H_ * S_ * D_];   // [bh, s, d]
__device__ float g_K[(size_t)B_ * H_ * S_ * D_];   // [bh, s, d]
__device__ float g_V[(size_t)B_ * H_ * S_ * D_];   // [bh, s, d]
__device__ float g_O[(size_t)B_ * S_ * H_ * D_];   // [b*s, h*d]

// ---------------------------------------------------------------------------
// mma.sync m16n8k8 tf32 helpers (compute_80+)
// Fragment maps (PTX ISA), g = lane>>2, t = lane&3:
//   A(16x8):  a0=(g,t) a1=(g+8,t) a2=(g,t+4) a3=(g+8,t+4)
//   B(8x8):   b0=(t,g) b1=(t+4,g)
//   D(16x8):  d0=(g,2t) d1=(g,2t+1) d2=(g+8,2t) d3=(g+8,2t+1)
// ---------------------------------------------------------------------------
__device__ __forceinline__ void mma_tf32(float* d, const uint32_t* a,
                                         uint32_t b0, uint32_t b1) {
    asm volatile(
        "mma.sync.aligned.m16n8k8.row.col.f32.tf32.tf32.f32 "
        "{%0,%1,%2,%3}, {%4,%5,%6,%7}, {%8,%9}, {%0,%1,%2,%3};"
        : "+f"(d[0]), "+f"(d[1]), "+f"(d[2]), "+f"(d[3])
        : "r"(a[0]), "r"(a[1]), "r"(a[2]), "r"(a[3]), "r"(b0), "r"(b1));
}

__device__ __forceinline__ float to_tf32(float x) {
    uint32_t u;
    asm("cvt.rna.tf32.f32 %0, %1;" : "=r"(u) : "f"(x));
    return __uint_as_float(u);
}

__device__ __forceinline__ float4 to_tf32_4(float4 v) {
    v.x = to_tf32(v.x); v.y = to_tf32(v.y);
    v.z = to_tf32(v.z); v.w = to_tf32(v.w);
    return v;
}

__device__ __forceinline__ uint32_t fbits(float x) { return __float_as_uint(x); }

// cp.async (Ampere+, no "a"-feature)
__device__ __forceinline__ void cp16(uint32_t dst, const void* src) {
    asm volatile("cp.async.cg.shared.global [%0], [%1], 16;\n"
                 :: "r"(dst), "l"(src));
}
#define CP_COMMIT() asm volatile("cp.async.commit_group;\n" ::: "memory")
#define CP_WAIT2()  asm volatile("cp.async.wait_group 2;\n" ::: "memory")

// ---------------------------------------------------------------------------
// TF32 tensor-core GEMM: C = A[M,1024] @ W[1024,N] + bias
// Tile 128x128, BK=16, cp.async 4-stage pipeline: one sync + one wait_group
// per k-step, no register staging, no STS on the critical path.
// tf32 rounding applied at fragment-load time (identical values to before).
// As stride 20 / Bs stride 136: conflict-free fragment LDS (verified).
// ---------------------------------------------------------------------------
#define AST 20
#define BST 136
#define AS_BYTES    (128 * AST * 4)            /* 10240 */
#define BS_BYTES    (16 * BST * 4)             /* 8704  */
#define STAGE_BYTES (AS_BYTES + BS_BYTES)      /* 18944 */
#define GEMM_SMEM   (4 * STAGE_BYTES)          /* 75776 */

template <int OUT_BHSD>
__global__ __launch_bounds__(256, 2)
void gemm_mma(const float* __restrict__ A, const float* __restrict__ W,
              const float* __restrict__ bias, float* __restrict__ C)
{
    extern __shared__ __align__(16) char gsm[];

    const int tid  = threadIdx.x;
    const int lane = tid & 31;
    const int wid  = tid >> 5;
    const int g = lane >> 2, t = lane & 3;
    const int wm = (wid & 1) * 64;
    const int wn = (wid >> 1) * 32;
    const int m0 = blockIdx.y * 128;
    const int n0 = blockIdx.x * 128;

    // Per-thread copy map: 2 A float4 + 2 B float4 per stage
    const int arow0 = tid >> 2,         ac0 = (tid & 3) * 4;
    const int arow1 = (tid + 256) >> 2, ac1 = ac0;
    const int brow0 = tid >> 5,         bc0 = (tid & 31) * 4;
    const int brow1 = brow0 + 8;
    const float* gA0 = A + (size_t)(m0 + arow0) * LAT_ + ac0;
    const float* gA1 = A + (size_t)(m0 + arow1) * LAT_ + ac1;
    const float* gB0 = W + (size_t)brow0 * LAT_ + n0 + bc0;
    const float* gB1 = W + (size_t)brow1 * LAT_ + n0 + bc0;
    const uint32_t sbase = (uint32_t)__cvta_generic_to_shared(gsm);
    const uint32_t dA0 = (arow0 * AST + ac0) * 4;
    const uint32_t dA1 = (arow1 * AST + ac1) * 4;
    const uint32_t dB0 = AS_BYTES + (brow0 * BST + bc0) * 4;
    const uint32_t dB1 = AS_BYTES + (brow1 * BST + bc0) * 4;

    float acc[4][4][4];
#pragma unroll
    for (int i = 0; i < 4; i++)
#pragma unroll
        for (int j = 0; j < 4; j++)
#pragma unroll
            for (int r = 0; r < 4; r++) acc[i][j][r] = 0.0f;

    // Prologue: stages 0..2 in flight
#pragma unroll
    for (int s = 0; s < 3; s++) {
        uint32_t buf = sbase + s * STAGE_BYTES;
        cp16(buf + dA0, gA0 + s * 16);
        cp16(buf + dA1, gA1 + s * 16);
        cp16(buf + dB0, gB0 + (size_t)(s * 16) * LAT_);
        cp16(buf + dB1, gB1 + (size_t)(s * 16) * LAT_);
        CP_COMMIT();
    }

    for (int kt = 0; kt < 64; kt++) {
        CP_WAIT2();            // group kt complete (<=2 newer pending)
        __syncthreads();       // all warps see stage kt; all done with kt-1
        if (kt + 3 < 64) {     // issue stage kt+3 (buffer (kt+3)&3 != kt&3)
            uint32_t buf = sbase + ((kt + 3) & 3) * STAGE_BYTES;
            cp16(buf + dA0, gA0 + (kt + 3) * 16);
            cp16(buf + dA1, gA1 + (kt + 3) * 16);
            cp16(buf + dB0, gB0 + (size_t)((kt + 3) * 16) * LAT_);
            cp16(buf + dB1, gB1 + (size_t)((kt + 3) * 16) * LAT_);
        }
        CP_COMMIT();           // commit every iteration (empty ok) for bookkeeping

        const float* As = (const float*)(gsm + (size_t)(kt & 3) * STAGE_BYTES);
        const float* Bs = (const float*)(gsm + (size_t)(kt & 3) * STAGE_BYTES + AS_BYTES);
#pragma unroll
        for (int ks = 0; ks < 2; ks++) {
            uint32_t a[4][4], b[4][2];
#pragma unroll
            for (int i = 0; i < 4; i++) {
                int base = (wm + i * 16 + g) * AST + ks * 8 + t;
                a[i][0] = fbits(to_tf32(As[base]));
                a[i][1] = fbits(to_tf32(As[base + 8 * AST]));
                a[i][2] = fbits(to_tf32(As[base + 4]));
                a[i][3] = fbits(to_tf32(As[base + 8 * AST + 4]));
            }
#pragma unroll
            for (int j = 0; j < 4; j++) {
                int base = (ks * 8 + t) * BST + wn + j * 8 + g;
                b[j][0] = fbits(to_tf32(Bs[base]));
                b[j][1] = fbits(to_tf32(Bs[base + 4 * BST]));
            }
#pragma unroll
            for (int i = 0; i < 4; i++)
#pragma unroll
                for (int j = 0; j < 4; j++)
                    mma_tf32(acc[i][j], a[i], b[j][0], b[j][1]);
        }
    }

    // Epilogue: fragment-direct float2 stores (+bias)
#pragma unroll
    for (int i = 0; i < 4; i++) {
        int r0 = m0 + wm + i * 16 + g;
#pragma unroll
        for (int j = 0; j < 4; j++) {
            int n = n0 + wn + j * 8 + 2 * t;
            float2 bb = *(const float2*)&bias[n];
            float2 v0 = { acc[i][j][0] + bb.x, acc[i][j][1] + bb.y };
            float2 v1 = { acc[i][j][2] + bb.x, acc[i][j][3] + bb.y };
            if (!OUT_BHSD) {
                *(float2*)(C + (size_t)r0 * LAT_ + n)       = v0;
                *(float2*)(C + (size_t)(r0 + 8) * LAT_ + n) = v1;
            } else {
                int bi = r0 >> 10, s = r0 & 1023;
                int h = n >> 6, d = n & 63;
                *(float2*)(C + (((size_t)(bi * H_ + h)) * S_ + s) * D_ + d)     = v0;
                *(float2*)(C + (((size_t)(bi * H_ + h)) * S_ + s + 8) * D_ + d) = v1;
            }
        }
    }
}

// ---------------------------------------------------------------------------
// Tensor-core flash attention (round-7 structure + shfl-built P fragments).
// Block: 128 queries, 256 threads (8 warps); warp w owns rows [16w, 16w+16).
// Smem (67584 B, 2 CTAs/SM):
//   Qf [wid][ks][lane] float4  A-frags of Q    (32 KB) -> LDS.128
//   Kf B-frags of QK^T (17408 B) | Vf B-frags of PV (17408 B), stride 68.
// P never touches smem: its A-frags are built from score registers by
// quad-shfl (lane mapping verified in round 8).
// exp2-domain softmax (scores pre-scaled by 0.125*log2 e).
// ---------------------------------------------------------------------------
#define QF_OFF   0
#define KF_OFF   32768
#define VF_OFF   (32768 + 17408)
#define QTMP_OFF 32768                   /* transient 34816B = Kf+Vf region */
#define ATTN_SMEM (32768 + 2 * 17408)    /* 67584 B */
#define SCL 0.1803368801111244f   /* 0.125 * log2(e) */

__global__ __launch_bounds__(256, 2)
void attn_mma_kernel(const int* __restrict__ mask, float* __restrict__ Og)
{
    extern __shared__ __align__(16) char smem[];
    float* Qf   = (float*)(smem + QF_OFF);
    float* Kf   = (float*)(smem + KF_OFF);
    float* Vf   = (float*)(smem + VF_OFF);
    float* Qtmp = (float*)(smem + QTMP_OFF);

    const int tid  = threadIdx.x;
    const int lane = tid & 31;
    const int wid  = tid >> 5;
    const int g = lane >> 2, t = lane & 3;
    const int qbase = blockIdx.x * 128;
    const int bh    = blockIdx.y;
    const int wq    = wid * 16;

    // --- Stage Q row-major (tf32) into transient area (128 x 68) ---
    const float* Qp = g_Q + ((size_t)bh * S_ + qbase) * D_;
#pragma unroll
    for (int it = 0; it < 8; it++) {
        int idx = tid + it * 256;
        int row = idx >> 4, c4 = (idx & 15) * 4;
        *(float4*)&Qtmp[row * 68 + c4] =
            to_tf32_4(*(const float4*)(Qp + (size_t)row * D_ + c4));
    }
    __syncthreads();

    // --- Fragment-major Qf (reads conflict-free: bank 4g+t) ---
#pragma unroll
    for (int ks = 0; ks < 8; ks++) {
        float q0 = Qtmp[(wq + g) * 68 + ks * 8 + t];
        float q1 = Qtmp[(wq + g + 8) * 68 + ks * 8 + t];
        float q2 = Qtmp[(wq + g) * 68 + ks * 8 + t + 4];
        float q3 = Qtmp[(wq + g + 8) * 68 + ks * 8 + t + 4];
        float4 f = { q0, q1, q2, q3 };
        *(float4*)&Qf[wid * 1024 + ks * 128 + lane * 4] = f;
    }
    __syncthreads();   // Qtmp dead; Kf/Vf live from here

    float m0r = -INFINITY, m1r = -INFINITY, l0 = 0.0f, l1 = 0.0f;
    float oacc[8][4];
#pragma unroll
    for (int nt = 0; nt < 8; nt++)
#pragma unroll
        for (int r = 0; r < 4; r++) oacc[nt][r] = 0.0f;

    const int* mrow0 = mask + ((size_t)bh * S_ + (qbase + wq + g)) * S_;
    const int* mrow1 = mrow0 + 8 * S_;

    // V staging map (fixed per thread)
    const int vrp = tid >> 3, vc = tid & 7;
    const int vks = vrp >> 2, vt = vrp & 3, vr = vks * 8 + vt;

    // Shfl-P lane mapping (verified in round 8)
    const int srcA = (lane & 28) + (t >> 1);
    const int srcB = srcA + 2;
    const bool odd = (t & 1);

    for (int kt = 0; kt < 16; kt++) {
        const int kbase = kt * 64;

        // Mask prefetch for this tile (latency hidden behind staging + MMAs)
        int2 mk0[8], mk1[8];
#pragma unroll
        for (int nt = 0; nt < 8; nt++) {
            mk0[nt] = *(const int2*)&mrow0[kbase + nt * 8 + 2 * t];
            mk1[nt] = *(const int2*)&mrow1[kbase + nt * 8 + 2 * t];
        }

        // --- Stage K in fragment-pair order: 2 items/thread ---
#pragma unroll
        for (int it = 0; it < 2; it++) {
            int item = tid + it * 256;          // 0..511
            int r = item >> 3, c = item & 7;
            const float* gk = g_K + ((size_t)bh * S_ + kbase + r) * D_ + c * 8;
            float4 v0 = to_tf32_4(*(const float4*)gk);
            float4 v1 = to_tf32_4(*(const float4*)(gk + 4));
            float* dst = Kf + ((r >> 3) * 8 + c) * 68 + (r & 7) * 8;
            float4 w0 = { v0.x, v1.x, v0.y, v1.y };
            float4 w1 = { v0.z, v1.z, v0.w, v1.w };
            *(float4*)(dst)     = w0;
            *(float4*)(dst + 4) = w1;
        }
        // --- Stage V: row pair (vr, vr+4), 8-col block vc ---
        {
            const float* gv = g_V + ((size_t)bh * S_ + kbase + vr) * D_ + vc * 8;
            float4 a0 = to_tf32_4(*(const float4*)gv);
            float4 a1 = to_tf32_4(*(const float4*)(gv + 4));
            float4 b0 = to_tf32_4(*(const float4*)(gv + 4 * D_));
            float4 b1 = to_tf32_4(*(const float4*)(gv + 4 * D_ + 4));
            float* dst = Vf + (vks * 8 + vc) * 68 + vt * 2;
            float2 p;
            p.x = a0.x; p.y = b0.x; *(float2*)(dst + 0)  = p;
            p.x = a0.y; p.y = b0.y; *(float2*)(dst + 8)  = p;
            p.x = a0.z; p.y = b0.z; *(float2*)(dst + 16) = p;
            p.x = a0.w; p.y = b0.w; *(float2*)(dst + 24) = p;
            p.x = a1.x; p.y = b1.x; *(float2*)(dst + 32) = p;
            p.x = a1.y; p.y = b1.y; *(float2*)(dst + 40) = p;
            p.x = a1.z; p.y = b1.z; *(float2*)(dst + 48) = p;
            p.x = a1.w; p.y = b1.w; *(float2*)(dst + 56) = p;
        }
        __syncthreads();

        // --- S = Q @ K^T ---
        float sacc[8][4];
#pragma unroll
        for (int nt = 0; nt < 8; nt++)
#pragma unroll
            for (int r = 0; r < 4; r++) sacc[nt][r] = 0.0f;
#pragma unroll
        for (int ks = 0; ks < 8; ks++) {
            uint4 qf = *(const uint4*)&Qf[wid * 1024 + ks * 128 + lane * 4];
            uint32_t qa_[4] = { qf.x, qf.y, qf.z, qf.w };
#pragma unroll
            for (int nt = 0; nt < 8; nt++) {
                float2 kf = *(const float2*)&Kf[(nt * 8 + ks) * 68 + lane * 2];
                mma_tf32(sacc[nt], qa_, fbits(kf.x), fbits(kf.y));
            }
        }

        // --- Mask + exp2-scale, row maxima ---
        float rm0 = -INFINITY, rm1 = -INFINITY;
#pragma unroll
        for (int nt = 0; nt < 8; nt++) {
            sacc[nt][0] = mk0[nt].x ? sacc[nt][0] * SCL : -INFINITY;
            sacc[nt][1] = mk0[nt].y ? sacc[nt][1] * SCL : -INFINITY;
            sacc[nt][2] = mk1[nt].x ? sacc[nt][2] * SCL : -INFINITY;
            sacc[nt][3] = mk1[nt].y ? sacc[nt][3] * SCL : -INFINITY;
            rm0 = fmaxf(rm0, fmaxf(sacc[nt][0], sacc[nt][1]));
            rm1 = fmaxf(rm1, fmaxf(sacc[nt][2], sacc[nt][3]));
        }
#pragma unroll
        for (int off = 1; off <= 2; off <<= 1) {
            rm0 = fmaxf(rm0, __shfl_xor_sync(0xffffffffu, rm0, off));
            rm1 = fmaxf(rm1, __shfl_xor_sync(0xffffffffu, rm1, off));
        }
        float mn0 = fmaxf(m0r, rm0);
        float mn1 = fmaxf(m1r, rm1);
        float corr0 = (mn0 == -INFINITY) ? 1.0f : exp2f(m0r - mn0);
        float corr1 = (mn1 == -INFINITY) ? 1.0f : exp2f(m1r - mn1);
        m0r = mn0; m1r = mn1;

        // --- exp2 into sacc (P values stay in registers), row sums ---
        float rs0 = 0.0f, rs1 = 0.0f;
#pragma unroll
        for (int nt = 0; nt < 8; nt++) {
            float p0 = (sacc[nt][0] == -INFINITY) ? 0.0f : exp2f(sacc[nt][0] - mn0);
            float p1 = (sacc[nt][1] == -INFINITY) ? 0.0f : exp2f(sacc[nt][1] - mn0);
            float p2 = (sacc[nt][2] == -INFINITY) ? 0.0f : exp2f(sacc[nt][2] - mn1);
            float p3 = (sacc[nt][3] == -INFINITY) ? 0.0f : exp2f(sacc[nt][3] - mn1);
            sacc[nt][0] = p0; sacc[nt][1] = p1;
            sacc[nt][2] = p2; sacc[nt][3] = p3;
            rs0 += p0 + p1;  rs1 += p2 + p3;
        }
#pragma unroll
        for (int off = 1; off <= 2; off <<= 1) {
            rs0 += __shfl_xor_sync(0xffffffffu, rs0, off);
            rs1 += __shfl_xor_sync(0xffffffffu, rs1, off);
        }
        l0 = l0 * corr0 + rs0;
        l1 = l1 * corr1 + rs1;
#pragma unroll
        for (int nt = 0; nt < 8; nt++) {
            oacc[nt][0] *= corr0; oacc[nt][1] *= corr0;
            oacc[nt][2] *= corr1; oacc[nt][3] *= corr1;
        }

        // --- O += P @ V : P A-frags built by quad-shfl from score regs ---
#pragma unroll
        for (int ks = 0; ks < 8; ks++) {
            float a0 = __shfl_sync(0xffffffffu, sacc[ks][0], srcA);
            float a1 = __shfl_sync(0xffffffffu, sacc[ks][1], srcA);
            float a2 = __shfl_sync(0xffffffffu, sacc[ks][2], srcA);
            float a3 = __shfl_sync(0xffffffffu, sacc[ks][3], srcA);
            float b0 = __shfl_sync(0xffffffffu, sacc[ks][0], srcB);
            float b1 = __shfl_sync(0xffffffffu, sacc[ks][1], srcB);
            float b2 = __shfl_sync(0xffffffffu, sacc[ks][2], srcB);
            float b3 = __shfl_sync(0xffffffffu, sacc[ks][3], srcB);
            uint32_t pa_[4] = { fbits(odd ? a1 : a0), fbits(odd ? a3 : a2),
                                fbits(odd ? b1 : b0), fbits(odd ? b3 : b2) };
#pragma unroll
            for (int nt = 0; nt < 8; nt++) {
                float2 vf = *(const float2*)&Vf[(ks * 8 + nt) * 68 + lane * 2];
                mma_tf32(oacc[nt], pa_, fbits(vf.x), fbits(vf.y));
            }
        }
        __syncthreads();   // Kf/Vf reads done before next tile's staging
    }

    // --- Final normalize + write [b*s][h*64+d] ---
    const int b = bh >> 4;
    const int h = bh & 15;
    const int r0 = qbase + wq + g;
    float inv0 = 1.0f / l0, inv1 = 1.0f / l1;
#pragma unroll
    for (int nt = 0; nt < 8; nt++) {
        int col = h * D_ + nt * 8 + 2 * t;
        float2 v0 = { oacc[nt][0] * inv0, oacc[nt][1] * inv0 };
        float2 v1 = { oacc[nt][2] * inv1, oacc[nt][3] * inv1 };
        *(float2*)(Og + ((size_t)(b * S_ + r0)) * (H_ * D_) + col)     = v0;
        *(float2*)(Og + ((size_t)(b * S_ + r0 + 8)) * (H_ * D_) + col) = v1;
    }
}

// ---------------------------------------------------------------------------
// Launch
// ---------------------------------------------------------------------------
extern "C" void kernel_launch(void* const* d_in, const int* in_sizes, int n_in,
                              void* d_out, int out_size)
{
    const float* input  = (const float*)d_in[0];
    const float* latent = (const float*)d_in[1];
    const int*   mask   = (const int*)d_in[2];
    const float* Wq = (const float*)d_in[3];
    const float* bq = (const float*)d_in[4];
    const float* Wk = (const float*)d_in[5];
    const float* bk = (const float*)d_in[6];
    const float* Wv = (const float*)d_in[7];
    const float* bv = (const float*)d_in[8];
    const float* Wo = (const float*)d_in[9];
    const float* bo = (const float*)d_in[10];
    float* out = (float*)d_out;

    float *qp, *kp, *vp, *op;
    cudaGetSymbolAddress((void**)&qp, g_Q);
    cudaGetSymbolAddress((void**)&kp, g_K);
    cudaGetSymbolAddress((void**)&vp, g_V);
    cudaGetSymbolAddress((void**)&op, g_O);

    cudaFuncSetAttribute(gemm_mma<0>,
                         cudaFuncAttributeMaxDynamicSharedMemorySize, GEMM_SMEM);
    cudaFuncSetAttribute(gemm_mma<1>,
                         cudaFuncAttributeMaxDynamicSharedMemorySize, GEMM_SMEM);
    cudaFuncSetAttribute(attn_mma_kernel,
                         cudaFuncAttributeMaxDynamicSharedMemorySize, ATTN_SMEM);

    dim3 gg(LAT_ / 128, (B_ * S_) / 128);   // (8, 64)
    gemm_mma<1><<<gg, 256, GEMM_SMEM>>>(latent, Wq, bq, qp);
    gemm_mma<1><<<gg, 256, GEMM_SMEM>>>(input,  Wk, bk, kp);
    gemm_mma<1><<<gg, 256, GEMM_SMEM>>>(input,  Wv, bv, vp);

    dim3 ga(S_ / 128, B_ * H_);             // (8, 128)
    attn_mma_kernel<<<ga, 256, ATTN_SMEM>>>(mask, op);

    gemm_mma<0><<<gg, 256, GEMM_SMEM>>>(op, Wo, bo, out);
}